// round 10
// baseline (speedup 1.0000x reference)
#include <cuda_runtime.h>
#include <cuda_fp16.h>
#include <cstdint>

#define NN 100000
#define NE 1600000
#define NG 512
#define FIN 20
#define HID 128
#define OUTF 64
#define NSCAN_BLK ((NN + 1023) / 1024)   // 98

// ---------------- scratch (device globals; no allocation allowed) ----------------
__device__ __align__(16) float  g_ax[(size_t)NN * FIN];    // aggregated x (layer-1 pre-GEMM)
__device__ __align__(16) __half g_x16[(size_t)NN * 32];    // x * dinv[row], fp16, rows padded to 64B
__device__ __align__(16) __half g_h[(size_t)NN * HID];     // node features (post relu), fp16
__device__ __align__(16) __half g_xw[(size_t)NN * HID];    // gemm output * dinv[row], fp16
__device__ __align__(16) __half g_Wt[2][HID * HID];        // W2^T, W3^T in fp16 (n-major)
__device__ float g_dinv[NN];
__device__ int   g_deg[NN];                                // EDGE-only degree (self loop excluded)
__device__ int   g_rowptr[NN + 1];
__device__ int   g_cursor[NN];
__device__ int   g_col[NE];                                // CSR without self loops
__device__ int   g_part[NSCAN_BLK + 32];
__device__ int   g_gcnt[NG];
__device__ int   g_gstart[NG + 1];
__device__ int   g_is64;

// dtype-agnostic index load (edge_index/batch may be int32 or int64)
__device__ __forceinline__ int load_idx(const void* p, int is64, long long i) {
    if (is64) return (int)((const long long*)p)[i];
    return ((const int*)p)[i];
}

// ---------------- mma / ldmatrix wrappers ----------------
__device__ __forceinline__ void ldsm_x4(uint32_t addr, uint32_t& r0, uint32_t& r1,
                                        uint32_t& r2, uint32_t& r3) {
    asm volatile("ldmatrix.sync.aligned.m8n8.x4.shared.b16 {%0,%1,%2,%3}, [%4];"
                 : "=r"(r0), "=r"(r1), "=r"(r2), "=r"(r3) : "r"(addr));
}
__device__ __forceinline__ void ldsm_x2(uint32_t addr, uint32_t& r0, uint32_t& r1) {
    asm volatile("ldmatrix.sync.aligned.m8n8.x2.shared.b16 {%0,%1}, [%2];"
                 : "=r"(r0), "=r"(r1) : "r"(addr));
}
__device__ __forceinline__ void mma16816(float* c, uint32_t a0, uint32_t a1, uint32_t a2,
                                         uint32_t a3, uint32_t b0, uint32_t b1) {
    asm volatile(
        "mma.sync.aligned.m16n8k16.row.col.f32.f16.f16.f32 "
        "{%0,%1,%2,%3},{%4,%5,%6,%7},{%8,%9},{%0,%1,%2,%3};"
        : "+f"(c[0]), "+f"(c[1]), "+f"(c[2]), "+f"(c[3])
        : "r"(a0), "r"(a1), "r"(a2), "r"(a3), "r"(b0), "r"(b1));
}

// ---------------- setup kernels ----------------
__global__ void k_detect(const int* __restrict__ ei32) {
    int z = 0;
    #pragma unroll
    for (int i = 1; i < 64; i += 2) z |= ei32[i];
    g_is64 = (z == 0) ? 1 : 0;
}

__global__ void k_zero_gcnt() {
    int t = threadIdx.x;
    if (t < NG) g_gcnt[t] = 0;
}

__global__ void k_init(const void* __restrict__ batch) {
    int i = blockIdx.x * blockDim.x + threadIdx.x;
    if (i < NN) {
        g_deg[i] = 0;
        atomicAdd(&g_gcnt[load_idx(batch, g_is64, i)], 1);
    }
}

// 4 edges per thread, vectorized dst loads (NE divisible by 4)
__global__ void k_degcount(const void* __restrict__ ei) {
    int base = (blockIdx.x * blockDim.x + threadIdx.x) * 4;
    if (base >= NE) return;
    int d0, d1, d2, d3;
    if (g_is64) {
        const long long* dd = (const long long*)ei + NE;
        longlong2 a = *(const longlong2*)(dd + base);
        longlong2 b = *(const longlong2*)(dd + base + 2);
        d0 = (int)a.x; d1 = (int)a.y; d2 = (int)b.x; d3 = (int)b.y;
    } else {
        const int* dd = (const int*)ei + NE;
        int4 a = *(const int4*)(dd + base);
        d0 = a.x; d1 = a.y; d2 = a.z; d3 = a.w;
    }
    atomicAdd(&g_deg[d0], 1);
    atomicAdd(&g_deg[d1], 1);
    atomicAdd(&g_deg[d2], 1);
    atomicAdd(&g_deg[d3], 1);
}

// convert + transpose weights to fp16: g_Wt[w][n*128+k] = W[k*128+n]
__global__ void k_wconv(const float* __restrict__ W2, const float* __restrict__ W3) {
    int id = blockIdx.x * blockDim.x + threadIdx.x;  // 0..32767
    int w = id >> 14;
    int e = id & 16383;
    int n = e >> 7, k = e & 127;
    const float* W = w ? W3 : W2;
    g_Wt[w][n * HID + k] = __float2half_rn(W[k * HID + n]);
}

// ---------------- multi-block scan of g_deg -> g_rowptr/g_cursor (+dinv) ----------------
__global__ void k_scan_part() {
    int b = blockIdx.x, t = threadIdx.x;
    int base = b * 1024 + t * 4;
    int s = 0;
    #pragma unroll
    for (int i = 0; i < 4; i++) {
        int idx = base + i;
        if (idx < NN) s += g_deg[idx];
    }
    #pragma unroll
    for (int o = 16; o; o >>= 1) s += __shfl_down_sync(0xffffffffu, s, o);
    __shared__ int ws[8];
    if ((t & 31) == 0) ws[t >> 5] = s;
    __syncthreads();
    if (t == 0) {
        int tot = 0;
        #pragma unroll
        for (int i = 0; i < 8; i++) tot += ws[i];
        g_part[b] = tot;
    }
}

__global__ void k_scan_part2() {
    int t = threadIdx.x, lane = t & 31, w = t >> 5;
    __shared__ int wsum[4];
    int v = (t < NSCAN_BLK) ? g_part[t] : 0;
    int x = v;
    #pragma unroll
    for (int o = 1; o < 32; o <<= 1) {
        int y = __shfl_up_sync(0xffffffffu, x, o);
        if (lane >= o) x += y;
    }
    if (lane == 31) wsum[w] = x;
    __syncthreads();
    if (t == 0) {
        int run = 0;
        #pragma unroll
        for (int i = 0; i < 4; i++) { int tmp = wsum[i]; wsum[i] = run; run += tmp; }
    }
    __syncthreads();
    if (t < NSCAN_BLK) g_part[t] = x - v + wsum[w];
    if (t == 0) g_rowptr[NN] = NE;
}

__global__ void k_scan_final() {
    int b = blockIdx.x, t = threadIdx.x, lane = t & 31, w = t >> 5;
    int base = b * 1024 + t * 4;
    int v[4];
    int tsum = 0;
    #pragma unroll
    for (int i = 0; i < 4; i++) {
        v[i] = (base + i < NN) ? g_deg[base + i] : 0;
        tsum += v[i];
    }
    int x = tsum;
    #pragma unroll
    for (int o = 1; o < 32; o <<= 1) {
        int y = __shfl_up_sync(0xffffffffu, x, o);
        if (lane >= o) x += y;
    }
    __shared__ int wsum[8];
    if (lane == 31) wsum[w] = x;
    __syncthreads();
    if (t == 0) {
        int run = 0;
        #pragma unroll
        for (int i = 0; i < 8; i++) { int tmp = wsum[i]; wsum[i] = run; run += tmp; }
    }
    __syncthreads();
    int run = x - tsum + wsum[w] + g_part[b];
    #pragma unroll
    for (int i = 0; i < 4; i++) {
        if (base + i < NN) {
            g_rowptr[base + i] = run;
            g_cursor[base + i] = run;
            g_dinv[base + i] = rsqrtf((float)(v[i] + 1));   // +1 self loop
            run += v[i];
        }
    }
}

// x -> fp16, prescaled by dinv[row], rows padded to 32 halves (64B)
__global__ void k_xconv(const float* __restrict__ x) {
    int id = blockIdx.x * blockDim.x + threadIdx.x;  // NN*16 half2 slots
    if (id >= NN * 16) return;
    int row = id >> 4, c = id & 15;
    __half2 v = __floats2half2_rn(0.f, 0.f);
    if (c < 10) {
        float dn = g_dinv[row];
        float a = x[(size_t)row * FIN + c * 2] * dn;
        float b = x[(size_t)row * FIN + c * 2 + 1] * dn;
        v = __floats2half2_rn(a, b);
    }
    *(__half2*)&g_x16[(size_t)row * 32 + c * 2] = v;
}

// single-block exclusive scan of g_gcnt -> g_gstart
__global__ void k_scan_g() {
    int t = threadIdx.x, lane = t & 31, w = t >> 5;
    int nwarps = blockDim.x >> 5;
    __shared__ int wsum[32];
    int v = g_gcnt[t];
    int x = v;
    #pragma unroll
    for (int o = 1; o < 32; o <<= 1) {
        int y = __shfl_up_sync(0xffffffffu, x, o);
        if (lane >= o) x += y;
    }
    if (lane == 31) wsum[w] = x;
    __syncthreads();
    if (w == 0) {
        int s = (lane < nwarps) ? wsum[lane] : 0;
        #pragma unroll
        for (int o = 1; o < 32; o <<= 1) {
            int y = __shfl_up_sync(0xffffffffu, s, o);
            if (lane >= o) s += y;
        }
        wsum[lane] = s;
    }
    __syncthreads();
    int incl = x + (w > 0 ? wsum[w - 1] : 0);
    g_gstart[t] = incl - v;
    if (t == 0) g_gstart[NG] = wsum[31];
}

// 4 edges per thread, vectorized src/dst loads; self loops NOT scattered
__global__ void k_scatter(const void* __restrict__ ei) {
    int base = (blockIdx.x * blockDim.x + threadIdx.x) * 4;
    if (base >= NE) return;
    int s0, s1, s2, s3, d0, d1, d2, d3;
    if (g_is64) {
        const long long* ss = (const long long*)ei;
        const long long* dd = ss + NE;
        longlong2 a = *(const longlong2*)(ss + base);
        longlong2 b = *(const longlong2*)(ss + base + 2);
        s0 = (int)a.x; s1 = (int)a.y; s2 = (int)b.x; s3 = (int)b.y;
        a = *(const longlong2*)(dd + base);
        b = *(const longlong2*)(dd + base + 2);
        d0 = (int)a.x; d1 = (int)a.y; d2 = (int)b.x; d3 = (int)b.y;
    } else {
        const int* ss = (const int*)ei;
        const int* dd = ss + NE;
        int4 a = *(const int4*)(ss + base);
        s0 = a.x; s1 = a.y; s2 = a.z; s3 = a.w;
        a = *(const int4*)(dd + base);
        d0 = a.x; d1 = a.y; d2 = a.z; d3 = a.w;
    }
    g_col[atomicAdd(&g_cursor[d0], 1)] = s0;
    g_col[atomicAdd(&g_cursor[d1], 1)] = s1;
    g_col[atomicAdd(&g_cursor[d2], 1)] = s2;
    g_col[atomicAdd(&g_cursor[d3], 1)] = s3;
}

// ---------------- layer 1: aggregate prescaled fp16 x, then small GEMM ----------------
// g_ax[d] = dinv[d] * ( x16[d] + sum_e x16[s] ),  x16 already scaled by dinv[row]
__global__ void k_agg_x() {
    int wid = (blockIdx.x * blockDim.x + threadIdx.x) >> 5;
    int lane = threadIdx.x & 31;
    if (wid >= NN) return;
    int r = g_rowptr[wid], e = g_rowptr[wid + 1];
    float2 acc = make_float2(0.f, 0.f);
    if (lane < 16) {
        __half2 v = *(const __half2*)&g_x16[(size_t)wid * 32 + lane * 2];  // self loop
        acc = __half22float2(v);
    }
    int j = r;
    for (; j + 2 <= e; j += 2) {
        int sA = g_col[j], sB = g_col[j + 1];
        if (lane < 16) {
            __half2 vA = *(const __half2*)&g_x16[(size_t)sA * 32 + lane * 2];
            __half2 vB = *(const __half2*)&g_x16[(size_t)sB * 32 + lane * 2];
            float2 fA = __half22float2(vA), fB = __half22float2(vB);
            acc.x += fA.x + fB.x; acc.y += fA.y + fB.y;
        }
    }
    if (j < e) {
        int s = g_col[j];
        if (lane < 16) {
            float2 f = __half22float2(*(const __half2*)&g_x16[(size_t)s * 32 + lane * 2]);
            acc.x += f.x; acc.y += f.y;
        }
    }
    if (lane < 10) {
        float dn = g_dinv[wid];
        g_ax[(size_t)wid * FIN + lane * 2]     = acc.x * dn;
        g_ax[(size_t)wid * FIN + lane * 2 + 1] = acc.y * dn;
    }
}

// g_ax[N,20] @ W1[20,128] + b1, relu -> g_h (fp16). 64 nodes/block, 256 threads.
__global__ void k_gemm1(const float* __restrict__ W1, const float* __restrict__ b1) {
    __shared__ __align__(16) float Wsh[FIN * HID];
    __shared__ float xsh[64 * FIN];
    int t = threadIdx.x;
    int bn = blockIdx.x * 64;
    for (int i = t; i < FIN * HID; i += 256) Wsh[i] = W1[i];
    for (int i = t; i < 64 * FIN; i += 256) {
        int n = i / FIN, k = i % FIN;
        xsh[i] = (bn + n < NN) ? g_ax[(size_t)(bn + n) * FIN + k] : 0.0f;
    }
    __syncthreads();
    int g = t >> 5, c4 = (t & 31) * 4;
    float4 acc[8];
    #pragma unroll
    for (int i = 0; i < 8; i++) acc[i] = make_float4(0.f, 0.f, 0.f, 0.f);
    for (int k = 0; k < FIN; k++) {
        float4 wv = *(const float4*)&Wsh[k * HID + c4];
        #pragma unroll
        for (int i = 0; i < 8; i++) {
            float xv = xsh[(g * 8 + i) * FIN + k];
            acc[i].x += wv.x * xv; acc[i].y += wv.y * xv;
            acc[i].z += wv.z * xv; acc[i].w += wv.w * xv;
        }
    }
    float4 bb = *(const float4*)&b1[c4];
    #pragma unroll
    for (int i = 0; i < 8; i++) {
        int n = bn + g * 8 + i;
        if (n < NN) {
            float ox = fmaxf(acc[i].x + bb.x, 0.f), oy = fmaxf(acc[i].y + bb.y, 0.f);
            float oz = fmaxf(acc[i].z + bb.z, 0.f), ow = fmaxf(acc[i].w + bb.w, 0.f);
            __half2* p = (__half2*)&g_h[(size_t)n * HID + c4];
            p[0] = __floats2half2_rn(ox, oy);
            p[1] = __floats2half2_rn(oz, ow);
        }
    }
}

// ---------------- hidden GEMM: g_h[N,128] @ W[128,128], * dinv[row] -> g_xw fp16 ----------------
__global__ __launch_bounds__(256, 2) void k_gemm_mma(int widx) {
    __shared__ __align__(16) __half Ash[64 * HID];    // 16 KB, swizzled
    __shared__ __align__(16) __half Wsh[HID * HID];   // 32 KB, swizzled
    int t = threadIdx.x;
    int bn = blockIdx.x * 64;

    for (int i = t; i < 64 * 16; i += 256) {
        int row = i >> 4, ch = i & 15;
        int gr = bn + row;
        uint4 v = make_uint4(0u, 0u, 0u, 0u);
        if (gr < NN) v = *(const uint4*)&g_h[(size_t)gr * HID + ch * 8];
        *(uint4*)((char*)Ash + row * 256 + ((ch ^ (row & 7)) << 4)) = v;
    }
    const __half* Wt = g_Wt[widx];
    for (int i = t; i < 128 * 16; i += 256) {
        int row = i >> 4, ch = i & 15;
        uint4 v = *(const uint4*)&Wt[(size_t)row * HID + ch * 8];
        *(uint4*)((char*)Wsh + row * 256 + ((ch ^ (row & 7)) << 4)) = v;
    }
    __syncthreads();

    int w = t >> 5, lane = t & 31;
    int mb = (w & 3) * 16;
    int nb = (w >> 2) * 8;
    uint32_t AshB = (uint32_t)__cvta_generic_to_shared(Ash);
    uint32_t WshB = (uint32_t)__cvta_generic_to_shared(Wsh);

    float c[8][4];
    #pragma unroll
    for (int i = 0; i < 8; i++)
        #pragma unroll
        for (int j = 0; j < 4; j++) c[i][j] = 0.f;

    int sel = lane >> 3, r8 = lane & 7;
    #pragma unroll
    for (int ks = 0; ks < 8; ks++) {
        int arow = mb + r8 + ((sel & 1) << 3);
        int ach = ks * 2 + (sel >> 1);
        uint32_t a0, a1, a2, a3;
        ldsm_x4(AshB + arow * 256 + ((ach ^ (arow & 7)) << 4), a0, a1, a2, a3);
        int bch = ks * 2 + ((lane >> 3) & 1);
        #pragma unroll
        for (int nt = 0; nt < 8; nt++) {
            int brow = (nb + nt) * 8 + r8;
            uint32_t b0, b1;
            ldsm_x2(WshB + brow * 256 + ((bch ^ (brow & 7)) << 4), b0, b1);
            mma16816(c[nt], a0, a1, a2, a3, b0, b1);
        }
    }

    int r1 = bn + mb + (lane >> 2);
    int r2 = r1 + 8;
    float s1 = (r1 < NN) ? g_dinv[r1] : 0.f;
    float s2 = (r2 < NN) ? g_dinv[r2] : 0.f;
    #pragma unroll
    for (int nt = 0; nt < 8; nt++) {
        int col = (nb + nt) * 8 + (lane & 3) * 2;
        if (r1 < NN)
            *(__half2*)&g_xw[(size_t)r1 * HID + col] = __floats2half2_rn(c[nt][0] * s1, c[nt][1] * s1);
        if (r2 < NN)
            *(__half2*)&g_xw[(size_t)r2 * HID + col] = __floats2half2_rn(c[nt][2] * s2, c[nt][3] * s2);
    }
}

// ---------------- aggregation (hidden layers) ----------------
// g_h[d] = relu( dinv[d] * ( xw[d] + sum_e xw[s] ) + b ), xw scaled by dinv[row]
__global__ void k_agg_h(const float* __restrict__ bias) {
    int wid = (blockIdx.x * blockDim.x + threadIdx.x) >> 5;
    int lane = threadIdx.x & 31;
    if (wid >= NN) return;
    int r = g_rowptr[wid], e = g_rowptr[wid + 1];
    // self-loop term
    uint2 v0 = *(const uint2*)&g_xw[(size_t)wid * HID + lane * 4];
    float2 f0 = __half22float2(*(__half2*)&v0.x);
    float2 f1 = __half22float2(*(__half2*)&v0.y);
    float4 acc = make_float4(f0.x, f0.y, f1.x, f1.y);
    int j = r;
    for (; j + 2 <= e; j += 2) {
        int sA = g_col[j], sB = g_col[j + 1];
        uint2 vA = *(const uint2*)&g_xw[(size_t)sA * HID + lane * 4];
        uint2 vB = *(const uint2*)&g_xw[(size_t)sB * HID + lane * 4];
        float2 a0 = __half22float2(*(__half2*)&vA.x);
        float2 a1 = __half22float2(*(__half2*)&vA.y);
        float2 b0 = __half22float2(*(__half2*)&vB.x);
        float2 b1 = __half22float2(*(__half2*)&vB.y);
        acc.x += a0.x + b0.x; acc.y += a0.y + b0.y;
        acc.z += a1.x + b1.x; acc.w += a1.y + b1.y;
    }
    if (j < e) {
        int s = g_col[j];
        uint2 v = *(const uint2*)&g_xw[(size_t)s * HID + lane * 4];
        float2 a0 = __half22float2(*(__half2*)&v.x);
        float2 a1 = __half22float2(*(__half2*)&v.y);
        acc.x += a0.x; acc.y += a0.y; acc.z += a1.x; acc.w += a1.y;
    }
    float dn = g_dinv[wid];
    float4 b = *(const float4*)&bias[lane * 4];
    float ox = fmaxf(acc.x * dn + b.x, 0.f), oy = fmaxf(acc.y * dn + b.y, 0.f);
    float oz = fmaxf(acc.z * dn + b.z, 0.f), ow = fmaxf(acc.w * dn + b.w, 0.f);
    __half2* p = (__half2*)&g_h[(size_t)wid * HID + lane * 4];
    p[0] = __floats2half2_rn(ox, oy);
    p[1] = __floats2half2_rn(oz, ow);
}

// ---------------- mean-pool + output head ----------------
__global__ void k_pool(const float* __restrict__ Wout, const float* __restrict__ bout,
                       float* __restrict__ out) {
    int gg = blockIdx.x;
    int t = threadIdx.x;  // 128
    int st = g_gstart[gg], en = g_gstart[gg + 1];
    float acc = 0.f;
    for (int n = st; n < en; n++) acc += __half2float(g_h[(size_t)n * HID + t]);
    __shared__ float pooled[HID];
    float cnt = (float)(en - st);
    if (cnt < 1.f) cnt = 1.f;
    pooled[t] = acc / cnt;
    __syncthreads();
    if (t < OUTF) {
        float o = bout[t];
        #pragma unroll 8
        for (int k = 0; k < HID; k++) o += pooled[k] * Wout[k * OUTF + t];
        out[(size_t)gg * OUTF + t] = o;
    }
}

// ---------------- launcher ----------------
extern "C" void kernel_launch(void* const* d_in, const int* in_sizes, int n_in,
                              void* d_out, int out_size) {
    const float* x     = (const float*)d_in[0];
    const void*  ei    = d_in[1];
    const void*  batch = d_in[2];
    const float* W1 = (const float*)d_in[3];  const float* b1 = (const float*)d_in[4];
    const float* W2 = (const float*)d_in[5];  const float* b2 = (const float*)d_in[6];
    const float* W3 = (const float*)d_in[7];  const float* b3 = (const float*)d_in[8];
    const float* Wout = (const float*)d_in[9]; const float* bout = (const float*)d_in[10];
    float* out = (float*)d_out;

    k_detect<<<1, 1>>>((const int*)ei);
    k_zero_gcnt<<<1, 512>>>();
    k_init<<<(NN + 255) / 256, 256>>>(batch);
    k_degcount<<<(NE / 4 + 255) / 256, 256>>>(ei);
    k_wconv<<<64, 512>>>(W2, W3);
    k_scan_part<<<NSCAN_BLK, 256>>>();
    k_scan_part2<<<1, 128>>>();
    k_scan_final<<<NSCAN_BLK, 256>>>();
    k_xconv<<<(NN * 16 + 255) / 256, 256>>>(x);
    k_scan_g<<<1, 512>>>();
    k_scatter<<<(NE / 4 + 255) / 256, 256>>>(ei);

    const int agg_blocks = (NN + 7) / 8;     // warp per node
    const int mma_blocks = (NN + 63) / 64;

    // --- layer 1 ---
    k_agg_x<<<agg_blocks, 256>>>();
    k_gemm1<<<(NN + 63) / 64, 256>>>(W1, b1);
    // --- layer 2 ---
    k_gemm_mma<<<mma_blocks, 256>>>(0);
    k_agg_h<<<agg_blocks, 256>>>(b2);
    // --- layer 3 ---
    k_gemm_mma<<<mma_blocks, 256>>>(1);
    k_agg_h<<<agg_blocks, 256>>>(b3);

    // --- pool + head ---
    k_pool<<<NG, HID>>>(Wout, bout, out);
}

// round 12
// speedup vs baseline: 1.0288x; 1.0288x over previous
#include <cuda_runtime.h>
#include <cuda_fp16.h>
#include <cstdint>

#define NN 100000
#define NE 1600000
#define NG 512
#define FIN 20
#define HID 128
#define OUTF 64
#define NSCAN_BLK ((NN + 1023) / 1024)   // 98

// ---------------- scratch (device globals; no allocation allowed) ----------------
__device__ __align__(16) float  g_ax[(size_t)NN * FIN];    // aggregated x (layer-1 pre-GEMM)
__device__ __align__(16) __half g_x16[(size_t)NN * 32];    // x * dinv[row], fp16, rows padded to 64B
__device__ __align__(16) __half g_h[(size_t)NN * HID];     // node features (post relu), fp16
__device__ __align__(16) __half g_xw[(size_t)NN * HID];    // gemm output * dinv[row], fp16
__device__ __align__(16) __half g_Wt[2][HID * HID];        // W2^T, W3^T in fp16 (n-major)
__device__ float g_dinv[NN];
__device__ int   g_deg[NN];                                // EDGE-only degree (self loop excluded)
__device__ int   g_rowptr[NN + 1];
__device__ int   g_cursor[NN];
__device__ int   g_col[NE];                                // CSR without self loops
__device__ int   g_part[NSCAN_BLK + 32];
__device__ int   g_gcnt[NG];
__device__ int   g_gstart[NG + 1];
__device__ int   g_is64;

// dtype-agnostic index load (edge_index/batch may be int32 or int64)
__device__ __forceinline__ int load_idx(const void* p, int is64, long long i) {
    if (is64) return (int)((const long long*)p)[i];
    return ((const int*)p)[i];
}

// ---------------- mma / ldmatrix wrappers ----------------
__device__ __forceinline__ void ldsm_x4(uint32_t addr, uint32_t& r0, uint32_t& r1,
                                        uint32_t& r2, uint32_t& r3) {
    asm volatile("ldmatrix.sync.aligned.m8n8.x4.shared.b16 {%0,%1,%2,%3}, [%4];"
                 : "=r"(r0), "=r"(r1), "=r"(r2), "=r"(r3) : "r"(addr));
}
__device__ __forceinline__ void ldsm_x2(uint32_t addr, uint32_t& r0, uint32_t& r1) {
    asm volatile("ldmatrix.sync.aligned.m8n8.x2.shared.b16 {%0,%1}, [%2];"
                 : "=r"(r0), "=r"(r1) : "r"(addr));
}
__device__ __forceinline__ void mma16816(float* c, uint32_t a0, uint32_t a1, uint32_t a2,
                                         uint32_t a3, uint32_t b0, uint32_t b1) {
    asm volatile(
        "mma.sync.aligned.m16n8k16.row.col.f32.f16.f16.f32 "
        "{%0,%1,%2,%3},{%4,%5,%6,%7},{%8,%9},{%0,%1,%2,%3};"
        : "+f"(c[0]), "+f"(c[1]), "+f"(c[2]), "+f"(c[3])
        : "r"(a0), "r"(a1), "r"(a2), "r"(a3), "r"(b0), "r"(b1));
}

// ---------------- setup kernels ----------------
// thread 0: dtype detect; threads <NG: zero graph counters (one launch)
__global__ void k_detect(const int* __restrict__ ei32) {
    int t = threadIdx.x;
    if (t < NG) g_gcnt[t] = 0;
    if (t == 0) {
        int z = 0;
        #pragma unroll
        for (int i = 1; i < 64; i += 2) z |= ei32[i];
        g_is64 = (z == 0) ? 1 : 0;
    }
}

__global__ void k_init(const void* __restrict__ batch) {
    int i = blockIdx.x * blockDim.x + threadIdx.x;
    if (i < NN) {
        g_deg[i] = 0;
        atomicAdd(&g_gcnt[load_idx(batch, g_is64, i)], 1);
    }
}

// one edge per thread: max warp count hides the atomic latency
__global__ void k_degcount(const void* __restrict__ ei) {
    int e = blockIdx.x * blockDim.x + threadIdx.x;
    if (e < NE) {
        int d = load_idx(ei, g_is64, (long long)NE + e);
        atomicAdd(&g_deg[d], 1);
    }
}

// convert + transpose weights to fp16: g_Wt[w][n*128+k] = W[k*128+n]
__global__ void k_wconv(const float* __restrict__ W2, const float* __restrict__ W3) {
    int id = blockIdx.x * blockDim.x + threadIdx.x;  // 0..32767
    int w = id >> 14;
    int e = id & 16383;
    int n = e >> 7, k = e & 127;
    const float* W = w ? W3 : W2;
    g_Wt[w][n * HID + k] = __float2half_rn(W[k * HID + n]);
}

// ---------------- multi-block scan of g_deg -> g_rowptr/g_cursor (+dinv) ----------------
__global__ void k_scan_part() {
    int b = blockIdx.x, t = threadIdx.x;
    int base = b * 1024 + t * 4;
    int s = 0;
    #pragma unroll
    for (int i = 0; i < 4; i++) {
        int idx = base + i;
        if (idx < NN) s += g_deg[idx];
    }
    #pragma unroll
    for (int o = 16; o; o >>= 1) s += __shfl_down_sync(0xffffffffu, s, o);
    __shared__ int ws[8];
    if ((t & 31) == 0) ws[t >> 5] = s;
    __syncthreads();
    if (t == 0) {
        int tot = 0;
        #pragma unroll
        for (int i = 0; i < 8; i++) tot += ws[i];
        g_part[b] = tot;
    }
}

// fused: block 0 scans partials; block 1 scans graph counts
__global__ void k_scan_mid() {
    int t = threadIdx.x, lane = t & 31, w = t >> 5;
    if (blockIdx.x == 0) {
        // exclusive scan of g_part (threads < 128 participate)
        __shared__ int wsum[4];
        if (t < 128) {
            int v = (t < NSCAN_BLK) ? g_part[t] : 0;
            int x = v;
            #pragma unroll
            for (int o = 1; o < 32; o <<= 1) {
                int y = __shfl_up_sync(0xffffffffu, x, o);
                if (lane >= o) x += y;
            }
            if (lane == 31) wsum[w] = x;
            __syncthreads();
            if (t == 0) {
                int run = 0;
                #pragma unroll
                for (int i = 0; i < 4; i++) { int tmp = wsum[i]; wsum[i] = run; run += tmp; }
            }
            __syncthreads();
            if (t < NSCAN_BLK) g_part[t] = x - v + wsum[w];
            if (t == 0) g_rowptr[NN] = NE;
        } else {
            __syncthreads();
            __syncthreads();
        }
    } else {
        // exclusive scan of g_gcnt (512 threads)
        __shared__ int wsum[16];
        int v = g_gcnt[t];
        int x = v;
        #pragma unroll
        for (int o = 1; o < 32; o <<= 1) {
            int y = __shfl_up_sync(0xffffffffu, x, o);
            if (lane >= o) x += y;
        }
        if (lane == 31) wsum[w] = x;
        __syncthreads();
        if (w == 0 && lane < 16) {
            int s = wsum[lane];
            #pragma unroll
            for (int o = 1; o < 16; o <<= 1) {
                int y = __shfl_up_sync(0xffffu, s, o);
                if (lane >= o) s += y;
            }
            wsum[lane] = s;
        }
        __syncthreads();
        int incl = x + (w > 0 ? wsum[w - 1] : 0);
        g_gstart[t] = incl - v;
        if (t == 0) g_gstart[NG] = wsum[15];
    }
}

__global__ void k_scan_final() {
    int b = blockIdx.x, t = threadIdx.x, lane = t & 31, w = t >> 5;
    int base = b * 1024 + t * 4;
    int v[4];
    int tsum = 0;
    #pragma unroll
    for (int i = 0; i < 4; i++) {
        v[i] = (base + i < NN) ? g_deg[base + i] : 0;
        tsum += v[i];
    }
    int x = tsum;
    #pragma unroll
    for (int o = 1; o < 32; o <<= 1) {
        int y = __shfl_up_sync(0xffffffffu, x, o);
        if (lane >= o) x += y;
    }
    __shared__ int wsum[8];
    if (lane == 31) wsum[w] = x;
    __syncthreads();
    if (t == 0) {
        int run = 0;
        #pragma unroll
        for (int i = 0; i < 8; i++) { int tmp = wsum[i]; wsum[i] = run; run += tmp; }
    }
    __syncthreads();
    int run = x - tsum + wsum[w] + g_part[b];
    #pragma unroll
    for (int i = 0; i < 4; i++) {
        if (base + i < NN) {
            g_rowptr[base + i] = run;
            g_cursor[base + i] = run;
            g_dinv[base + i] = rsqrtf((float)(v[i] + 1));   // +1 self loop
            run += v[i];
        }
    }
}

// x -> fp16, prescaled by dinv[row], rows padded to 32 halves (64B)
__global__ void k_xconv(const float* __restrict__ x) {
    int id = blockIdx.x * blockDim.x + threadIdx.x;  // NN*16 half2 slots
    if (id >= NN * 16) return;
    int row = id >> 4, c = id & 15;
    __half2 v = __floats2half2_rn(0.f, 0.f);
    if (c < 10) {
        float dn = g_dinv[row];
        float a = x[(size_t)row * FIN + c * 2] * dn;
        float b = x[(size_t)row * FIN + c * 2 + 1] * dn;
        v = __floats2half2_rn(a, b);
    }
    *(__half2*)&g_x16[(size_t)row * 32 + c * 2] = v;
}

// one edge per thread; self loops NOT scattered
__global__ void k_scatter(const void* __restrict__ ei) {
    int e = blockIdx.x * blockDim.x + threadIdx.x;
    if (e >= NE) return;
    int s = load_idx(ei, g_is64, e);
    int d = load_idx(ei, g_is64, (long long)NE + e);
    int pos = atomicAdd(&g_cursor[d], 1);
    g_col[pos] = s;
}

// ---------------- layer 1: aggregate prescaled fp16 x, then small GEMM ----------------
// g_ax[d] = dinv[d] * ( x16[d] + sum_e x16[s] ),  x16 already scaled by dinv[row]
__global__ void k_agg_x() {
    int wid = (blockIdx.x * blockDim.x + threadIdx.x) >> 5;
    int lane = threadIdx.x & 31;
    if (wid >= NN) return;
    int r = g_rowptr[wid], e = g_rowptr[wid + 1];
    float2 acc = make_float2(0.f, 0.f);
    if (lane < 16) {
        __half2 v = *(const __half2*)&g_x16[(size_t)wid * 32 + lane * 2];  // self loop
        acc = __half22float2(v);
    }
    int j = r;
    for (; j + 2 <= e; j += 2) {
        int sA = g_col[j], sB = g_col[j + 1];
        if (lane < 16) {
            __half2 vA = *(const __half2*)&g_x16[(size_t)sA * 32 + lane * 2];
            __half2 vB = *(const __half2*)&g_x16[(size_t)sB * 32 + lane * 2];
            float2 fA = __half22float2(vA), fB = __half22float2(vB);
            acc.x += fA.x + fB.x; acc.y += fA.y + fB.y;
        }
    }
    if (j < e) {
        int s = g_col[j];
        if (lane < 16) {
            float2 f = __half22float2(*(const __half2*)&g_x16[(size_t)s * 32 + lane * 2]);
            acc.x += f.x; acc.y += f.y;
        }
    }
    if (lane < 10) {
        float dn = g_dinv[wid];
        g_ax[(size_t)wid * FIN + lane * 2]     = acc.x * dn;
        g_ax[(size_t)wid * FIN + lane * 2 + 1] = acc.y * dn;
    }
}

// g_ax[N,20] @ W1[20,128] + b1, relu -> g_h (fp16). 64 nodes/block, 256 threads.
__global__ void k_gemm1(const float* __restrict__ W1, const float* __restrict__ b1) {
    __shared__ __align__(16) float Wsh[FIN * HID];
    __shared__ float xsh[64 * FIN];
    int t = threadIdx.x;
    int bn = blockIdx.x * 64;
    for (int i = t; i < FIN * HID; i += 256) Wsh[i] = W1[i];
    for (int i = t; i < 64 * FIN; i += 256) {
        int n = i / FIN, k = i % FIN;
        xsh[i] = (bn + n < NN) ? g_ax[(size_t)(bn + n) * FIN + k] : 0.0f;
    }
    __syncthreads();
    int g = t >> 5, c4 = (t & 31) * 4;
    float4 acc[8];
    #pragma unroll
    for (int i = 0; i < 8; i++) acc[i] = make_float4(0.f, 0.f, 0.f, 0.f);
    for (int k = 0; k < FIN; k++) {
        float4 wv = *(const float4*)&Wsh[k * HID + c4];
        #pragma unroll
        for (int i = 0; i < 8; i++) {
            float xv = xsh[(g * 8 + i) * FIN + k];
            acc[i].x += wv.x * xv; acc[i].y += wv.y * xv;
            acc[i].z += wv.z * xv; acc[i].w += wv.w * xv;
        }
    }
    float4 bb = *(const float4*)&b1[c4];
    #pragma unroll
    for (int i = 0; i < 8; i++) {
        int n = bn + g * 8 + i;
        if (n < NN) {
            float ox = fmaxf(acc[i].x + bb.x, 0.f), oy = fmaxf(acc[i].y + bb.y, 0.f);
            float oz = fmaxf(acc[i].z + bb.z, 0.f), ow = fmaxf(acc[i].w + bb.w, 0.f);
            __half2* p = (__half2*)&g_h[(size_t)n * HID + c4];
            p[0] = __floats2half2_rn(ox, oy);
            p[1] = __floats2half2_rn(oz, ow);
        }
    }
}

// ---------------- hidden GEMM: g_h[N,128] @ W[128,128], * dinv[row] -> g_xw fp16 ----------------
__global__ __launch_bounds__(256, 2) void k_gemm_mma(int widx) {
    __shared__ __align__(16) __half Ash[64 * HID];    // 16 KB, swizzled
    __shared__ __align__(16) __half Wsh[HID * HID];   // 32 KB, swizzled
    int t = threadIdx.x;
    int bn = blockIdx.x * 64;

    for (int i = t; i < 64 * 16; i += 256) {
        int row = i >> 4, ch = i & 15;
        int gr = bn + row;
        uint4 v = make_uint4(0u, 0u, 0u, 0u);
        if (gr < NN) v = *(const uint4*)&g_h[(size_t)gr * HID + ch * 8];
        *(uint4*)((char*)Ash + row * 256 + ((ch ^ (row & 7)) << 4)) = v;
    }
    const __half* Wt = g_Wt[widx];
    for (int i = t; i < 128 * 16; i += 256) {
        int row = i >> 4, ch = i & 15;
        uint4 v = *(const uint4*)&Wt[(size_t)row * HID + ch * 8];
        *(uint4*)((char*)Wsh + row * 256 + ((ch ^ (row & 7)) << 4)) = v;
    }
    __syncthreads();

    int w = t >> 5, lane = t & 31;
    int mb = (w & 3) * 16;
    int nb = (w >> 2) * 8;
    uint32_t AshB = (uint32_t)__cvta_generic_to_shared(Ash);
    uint32_t WshB = (uint32_t)__cvta_generic_to_shared(Wsh);

    float c[8][4];
    #pragma unroll
    for (int i = 0; i < 8; i++)
        #pragma unroll
        for (int j = 0; j < 4; j++) c[i][j] = 0.f;

    int sel = lane >> 3, r8 = lane & 7;
    #pragma unroll
    for (int ks = 0; ks < 8; ks++) {
        int arow = mb + r8 + ((sel & 1) << 3);
        int ach = ks * 2 + (sel >> 1);
        uint32_t a0, a1, a2, a3;
        ldsm_x4(AshB + arow * 256 + ((ach ^ (arow & 7)) << 4), a0, a1, a2, a3);
        int bch = ks * 2 + ((lane >> 3) & 1);
        #pragma unroll
        for (int nt = 0; nt < 8; nt++) {
            int brow = (nb + nt) * 8 + r8;
            uint32_t b0, b1;
            ldsm_x2(WshB + brow * 256 + ((bch ^ (brow & 7)) << 4), b0, b1);
            mma16816(c[nt], a0, a1, a2, a3, b0, b1);
        }
    }

    int r1 = bn + mb + (lane >> 2);
    int r2 = r1 + 8;
    float s1 = (r1 < NN) ? g_dinv[r1] : 0.f;
    float s2 = (r2 < NN) ? g_dinv[r2] : 0.f;
    #pragma unroll
    for (int nt = 0; nt < 8; nt++) {
        int col = (nb + nt) * 8 + (lane & 3) * 2;
        if (r1 < NN)
            *(__half2*)&g_xw[(size_t)r1 * HID + col] = __floats2half2_rn(c[nt][0] * s1, c[nt][1] * s1);
        if (r2 < NN)
            *(__half2*)&g_xw[(size_t)r2 * HID + col] = __floats2half2_rn(c[nt][2] * s2, c[nt][3] * s2);
    }
}

// ---------------- aggregation (hidden layers) ----------------
// g_h[d] = relu( dinv[d] * ( xw[d] + sum_e xw[s] ) + b ), xw scaled by dinv[row]
__global__ void k_agg_h(const float* __restrict__ bias) {
    int wid = (blockIdx.x * blockDim.x + threadIdx.x) >> 5;
    int lane = threadIdx.x & 31;
    if (wid >= NN) return;
    int r = g_rowptr[wid], e = g_rowptr[wid + 1];
    // self-loop term
    uint2 v0 = *(const uint2*)&g_xw[(size_t)wid * HID + lane * 4];
    float2 f0 = __half22float2(*(__half2*)&v0.x);
    float2 f1 = __half22float2(*(__half2*)&v0.y);
    float4 acc = make_float4(f0.x, f0.y, f1.x, f1.y);
    int j = r;
    for (; j + 2 <= e; j += 2) {
        int sA = g_col[j], sB = g_col[j + 1];
        uint2 vA = *(const uint2*)&g_xw[(size_t)sA * HID + lane * 4];
        uint2 vB = *(const uint2*)&g_xw[(size_t)sB * HID + lane * 4];
        float2 a0 = __half22float2(*(__half2*)&vA.x);
        float2 a1 = __half22float2(*(__half2*)&vA.y);
        float2 b0 = __half22float2(*(__half2*)&vB.x);
        float2 b1 = __half22float2(*(__half2*)&vB.y);
        acc.x += a0.x + b0.x; acc.y += a0.y + b0.y;
        acc.z += a1.x + b1.x; acc.w += a1.y + b1.y;
    }
    if (j < e) {
        int s = g_col[j];
        uint2 v = *(const uint2*)&g_xw[(size_t)s * HID + lane * 4];
        float2 a0 = __half22float2(*(__half2*)&v.x);
        float2 a1 = __half22float2(*(__half2*)&v.y);
        acc.x += a0.x; acc.y += a0.y; acc.z += a1.x; acc.w += a1.y;
    }
    float dn = g_dinv[wid];
    float4 b = *(const float4*)&bias[lane * 4];
    float ox = fmaxf(acc.x * dn + b.x, 0.f), oy = fmaxf(acc.y * dn + b.y, 0.f);
    float oz = fmaxf(acc.z * dn + b.z, 0.f), ow = fmaxf(acc.w * dn + b.w, 0.f);
    __half2* p = (__half2*)&g_h[(size_t)wid * HID + lane * 4];
    p[0] = __floats2half2_rn(ox, oy);
    p[1] = __floats2half2_rn(oz, ow);
}

// ---------------- mean-pool + output head ----------------
__global__ void k_pool(const float* __restrict__ Wout, const float* __restrict__ bout,
                       float* __restrict__ out) {
    int gg = blockIdx.x;
    int t = threadIdx.x;  // 128
    int st = g_gstart[gg], en = g_gstart[gg + 1];
    float acc = 0.f;
    for (int n = st; n < en; n++) acc += __half2float(g_h[(size_t)n * HID + t]);
    __shared__ float pooled[HID];
    float cnt = (float)(en - st);
    if (cnt < 1.f) cnt = 1.f;
    pooled[t] = acc / cnt;
    __syncthreads();
    if (t < OUTF) {
        float o = bout[t];
        #pragma unroll 8
        for (int k = 0; k < HID; k++) o += pooled[k] * Wout[k * OUTF + t];
        out[(size_t)gg * OUTF + t] = o;
    }
}

// ---------------- launcher ----------------
extern "C" void kernel_launch(void* const* d_in, const int* in_sizes, int n_in,
                              void* d_out, int out_size) {
    const float* x     = (const float*)d_in[0];
    const void*  ei    = d_in[1];
    const void*  batch = d_in[2];
    const float* W1 = (const float*)d_in[3];  const float* b1 = (const float*)d_in[4];
    const float* W2 = (const float*)d_in[5];  const float* b2 = (const float*)d_in[6];
    const float* W3 = (const float*)d_in[7];  const float* b3 = (const float*)d_in[8];
    const float* Wout = (const float*)d_in[9]; const float* bout = (const float*)d_in[10];
    float* out = (float*)d_out;

    k_detect<<<1, 512>>>((const int*)ei);
    k_init<<<(NN + 255) / 256, 256>>>(batch);
    k_degcount<<<(NE + 255) / 256, 256>>>(ei);
    k_wconv<<<64, 512>>>(W2, W3);
    k_scan_part<<<NSCAN_BLK, 256>>>();
    k_scan_mid<<<2, 512>>>();
    k_scan_final<<<NSCAN_BLK, 256>>>();
    k_xconv<<<(NN * 16 + 255) / 256, 256>>>(x);
    k_scatter<<<(NE + 255) / 256, 256>>>(ei);

    const int agg_blocks = (NN + 7) / 8;     // warp per node
    const int mma_blocks = (NN + 63) / 64;

    // --- layer 1 ---
    k_agg_x<<<agg_blocks, 256>>>();
    k_gemm1<<<(NN + 63) / 64, 256>>>(W1, b1);
    // --- layer 2 ---
    k_gemm_mma<<<mma_blocks, 256>>>(0);
    k_agg_h<<<agg_blocks, 256>>>(b2);
    // --- layer 3 ---
    k_gemm_mma<<<mma_blocks, 256>>>(1);
    k_agg_h<<<agg_blocks, 256>>>(b3);

    // --- pool + head ---
    k_pool<<<NG, HID>>>(Wout, bout, out);
}